// round 7
// baseline (speedup 1.0000x reference)
#include <cuda_runtime.h>
#include <cuda_bf16.h>

#define NTAGS 64
#define LOG2E 1.4426950408889634f
#define LN2   0.69314718055994531f

__device__ __forceinline__ float fast_ex2(float x) {
    float r; asm("ex2.approx.ftz.f32 %0, %1;" : "=f"(r) : "f"(x)); return r;
}
__device__ __forceinline__ float fast_lg2(float x) {
    float r; asm("lg2.approx.ftz.f32 %0, %1;" : "=f"(r) : "f"(x)); return r;
}
__device__ __forceinline__ void fma2(unsigned long long& d, unsigned long long a, unsigned long long b) {
    asm("fma.rn.f32x2 %0, %1, %2, %0;" : "+l"(d) : "l"(a), "l"(b));
}
__device__ __forceinline__ unsigned long long add2(unsigned long long a, unsigned long long b) {
    unsigned long long r; asm("add.rn.f32x2 %0, %1, %2;" : "=l"(r) : "l"(a), "l"(b)); return r;
}
__device__ __forceinline__ unsigned long long pack2(float x, float y) {
    unsigned long long r; asm("mov.b64 %0, {%1, %2};" : "=l"(r) : "f"(x), "f"(y)); return r;
}
__device__ __forceinline__ float2 unpack2(unsigned long long v) {
    float2 f; asm("mov.b64 {%0, %1}, %2;" : "=f"(f.x), "=f"(f.y) : "l"(v)); return f;
}

// Named barrier over 64 threads (one group = 2 warps).
#define GROUP_BAR(id) asm volatile("bar.sync %0, 64;" :: "r"(id) : "memory")

// One CTA (256 threads) = TWO batch pairs, each TIME-SPLIT into fwd/bwd groups:
//   group 0 (warps 0,1 / SMSP 0,1): pair0 FORWARD   P <- diag(f_t) E P, t ascending
//   group 1 (warps 2,3 / SMSP 2,3): pair0 BACKWARD  A <- E^T (f_t (*) A), t descending
//   group 2 (warps 4,5 / SMSP 0,1): pair1 FORWARD
//   group 3 (warps 6,7 / SMSP 2,3): pair1 BACKWARD
// grid = B/4 = 128 -> exactly one CTA per SM. Every SMSP hosts two warps from
// INDEPENDENT groups, so each serial chain's latency (LDS, FFMA tail, barrier)
// is hidden by the other chain's issue — guaranteed, not a co-residency lottery.
// Groups sync only with themselves via named barriers and run only their own
// round count (fwd: ceil(len/2), bwd: floor(len/2)).
//
// Linear-domain normalization per round: divide the stored vector by its
// element 0 (q), accumulate lg2(q); emission factor folded via
// ex2(emit*log2e - lg2 q) on MUFU, overlapped with the 64-term f32x2 dot.
// The backward state always carries one extra folded emission, divided out
// in the epilogue. answer = LN2*(m2F + m2B + lg2(dot(P, A))).
__global__ __launch_bounds__(256, 1)
void crf_fwd_kernel(const float* __restrict__ h, const float* __restrict__ trans,
                    const int* __restrict__ lengths, float* __restrict__ out,
                    int B, int T)
{
    const int tid   = threadIdx.x;
    const int g     = tid >> 6;            // group 0..3
    const int tag   = tid & 63;
    const int dir   = g & 1;               // 0 = forward, 1 = backward
    const int pair  = g >> 1;              // 0 or 1
    const int barid = g + 1;

    const int b0v = blockIdx.x * 4 + pair * 2;
    const int b1v = b0v + 1;
    const int b0  = min(b0v, B - 1);
    const int b1  = min(b1v, B - 1);

    __shared__ __align__(16) unsigned long long pbuf[4][2][NTAGS]; // [group][buf][tag]
    __shared__ __align__(16) unsigned long long fin[4][NTAGS];     // final vectors
    __shared__ float2 fm2[4];                                      // log2 normalizer sums

    const int len0 = lengths[b0];
    const int len1 = lengths[b1];
    const int mid0 = (len0 + 1) >> 1;
    const int mid1 = (len1 + 1) >> 1;
    const int act0 = dir ? (len0 - mid0) : mid0;  // active rounds per component
    const int act1 = dir ? (len1 - mid1) : mid1;
    const int rounds = max(act0, act1);           // group-local bound

    // cache exp(trans): fwd lanes cache row `tag`, bwd lanes cache column `tag`
    unsigned long long rowp[NTAGS];
    {
        const int base   = dir ? tag : tag * NTAGS;
        const int stride = dir ? NTAGS : 1;
        #pragma unroll
        for (int j = 0; j < NTAGS; j++) {
            float e = fast_ex2(trans[base + j * stride] * LOG2E);
            rowp[j] = pack2(e, e);
        }
    }

    const float* __restrict__ hb0 = h + (size_t)b0 * T * NTAGS + tag;
    const float* __restrict__ hb1 = h + (size_t)b1 * T * NTAGS + tag;

    // initial state
    float px, py, el0 = 0.0f, el1 = 0.0f;  // el* = most recent folded emission (bwd)
    if (dir == 0) {
        px = (tag == NTAGS - 2) ? 1.0f : 0.0f;   // START_TAG = N-2
        py = px;
    } else {
        float uval = fast_ex2(trans[(NTAGS - 1) * NTAGS + tag] * LOG2E); // END row
        el0 = hb0[(size_t)(len0 - 1) * NTAGS];
        el1 = hb1[(size_t)(len1 - 1) * NTAGS];
        px = uval * fast_ex2(el0 * LOG2E);
        py = uval * fast_ex2(el1 * LOG2E);
    }
    float m20 = 0.0f, m21 = 0.0f;

    pbuf[g][0][tag] = pack2(px, py);
    GROUP_BAR(barid);

    // emission pipeline, 2 deep. index at round r: fwd r ; bwd max(len-2-r, 0)
    const int Tm1 = T - 1;
    int i0a = dir ? max(len0 - 2, 0) : 0;
    int i1a = dir ? max(len1 - 2, 0) : 0;
    int i0b = dir ? max(len0 - 3, 0) : min(1, Tm1);
    int i1b = dir ? max(len1 - 3, 0) : min(1, Tm1);
    float ea0 = hb0[(size_t)i0a * NTAGS];
    float ea1 = hb1[(size_t)i1a * NTAGS];
    float eb0 = hb0[(size_t)i0b * NTAGS];
    float eb1 = hb1[(size_t)i1b * NTAGS];

    int buf = 0;
    for (int r = 0; r < rounds; r++) {
        const ulonglong2* Pv = reinterpret_cast<const ulonglong2*>(pbuf[g][buf]);

        ulonglong2 u0 = Pv[0], u1 = Pv[1], u2 = Pv[2], u3 = Pv[3];
        float2 qq = unpack2(u0.x);                 // normalizer q = vec[0]
        const bool q1sel = (dir == 0) & (r == 0);  // fwd round 0: vec[0] == 0
        float qx = q1sel ? 1.0f : qq.x;
        float qy = q1sel ? 1.0f : qq.y;

        unsigned long long a0 = 0, a1 = 0, a2 = 0, a3 = 0;
        unsigned long long a4 = 0, a5 = 0, a6 = 0, a7 = 0;
        fma2(a0, rowp[0], u0.x); fma2(a1, rowp[1], u0.y);
        fma2(a2, rowp[2], u1.x); fma2(a3, rowp[3], u1.y);
        fma2(a4, rowp[4], u2.x); fma2(a5, rowp[5], u2.y);
        fma2(a6, rowp[6], u3.x); fma2(a7, rowp[7], u3.y);

        // normalizer + emission factor on MUFU, overlapped with the dot
        float l2x = fast_lg2(qx);
        float l2y = fast_lg2(qy);
        float rx  = fast_ex2(fmaf(ea0, LOG2E, -l2x));
        float ry  = fast_ex2(fmaf(ea1, LOG2E, -l2y));

        #pragma unroll
        for (int k = 4; k < 32; k += 4) {
            ulonglong2 v0 = Pv[k],     v1 = Pv[k + 1];
            ulonglong2 v2 = Pv[k + 2], v3 = Pv[k + 3];
            fma2(a0, rowp[2 * k + 0], v0.x); fma2(a1, rowp[2 * k + 1], v0.y);
            fma2(a2, rowp[2 * k + 2], v1.x); fma2(a3, rowp[2 * k + 3], v1.y);
            fma2(a4, rowp[2 * k + 4], v2.x); fma2(a5, rowp[2 * k + 5], v2.y);
            fma2(a6, rowp[2 * k + 6], v3.x); fma2(a7, rowp[2 * k + 7], v3.y);
        }

        // prefetch emissions for round r+2 (clamped, memory-safe)
        int n0 = dir ? max(len0 - 4 - r, 0) : min(r + 2, Tm1);
        int n1 = dir ? max(len1 - 4 - r, 0) : min(r + 2, Tm1);
        float ec0 = hb0[(size_t)n0 * NTAGS];
        float ec1 = hb1[(size_t)n1 * NTAGS];

        float2 S = unpack2(add2(add2(add2(a0, a1), add2(a2, a3)),
                                add2(add2(a4, a5), add2(a6, a7))));

        // masked update (freeze past this component's active rounds)
        const bool k0 = r < act0;
        const bool k1 = r < act1;
        px   = k0 ? S.x * rx : px;   m20 += k0 ? l2x : 0.0f;
        py   = k1 ? S.y * ry : py;   m21 += k1 ? l2y : 0.0f;
        el0  = k0 ? ea0 : el0;       // emission currently folded (bwd bookkeeping)
        el1  = k1 ? ea1 : el1;

        pbuf[g][buf ^ 1][tag] = pack2(px, py);
        GROUP_BAR(barid);

        ea0 = eb0; ea1 = eb1;
        eb0 = ec0; eb1 = ec1;
        buf ^= 1;
    }

    // Backward state carries one extra folded emission: divide it out.
    float c0 = dir ? fast_ex2(-el0 * LOG2E) : 1.0f;
    float c1 = dir ? fast_ex2(-el1 * LOG2E) : 1.0f;
    fin[g][tag] = pack2(px * c0, py * c1);
    if (tag == 0) fm2[g] = make_float2(m20, m21);
    __syncthreads();

    // Epilogue: warp p reduces pair p. answer = LN2*(m2F + m2B + lg2(F . A)).
    if (tid < 64) {
        const int p    = tid >> 5;
        const int lane = tid & 31;
        float2 Fa = unpack2(fin[2 * p][lane]);
        float2 Fb = unpack2(fin[2 * p][lane + 32]);
        float2 Aa = unpack2(fin[2 * p + 1][lane]);
        float2 Ab = unpack2(fin[2 * p + 1][lane + 32]);
        float sx = Fa.x * Aa.x + Fb.x * Ab.x;
        float sy = Fa.y * Aa.y + Fb.y * Ab.y;
        #pragma unroll
        for (int o = 16; o > 0; o >>= 1) {
            sx += __shfl_xor_sync(0xffffffffu, sx, o);
            sy += __shfl_xor_sync(0xffffffffu, sy, o);
        }
        if (lane == 0) {
            float2 mF = fm2[2 * p];
            float2 mB = fm2[2 * p + 1];
            const int ob0 = blockIdx.x * 4 + p * 2;
            if (ob0 < B)     out[ob0]     = LN2 * (mF.x + mB.x + fast_lg2(sx));
            if (ob0 + 1 < B) out[ob0 + 1] = LN2 * (mF.y + mB.y + fast_lg2(sy));
        }
    }
}

extern "C" void kernel_launch(void* const* d_in, const int* in_sizes, int n_in,
                              void* d_out, int out_size)
{
    const float* h       = (const float*)d_in[0];   // [B, T, N] f32
    const float* trans   = (const float*)d_in[1];   // [N, N]    f32
    const int*   lengths = (const int*)d_in[2];     // [B]       i32
    float*       out     = (float*)d_out;           // [B]       f32

    const int B = in_sizes[2];
    const int T = in_sizes[0] / (B * NTAGS);

    const int nblk = (B + 3) / 4;
    crf_fwd_kernel<<<nblk, 256>>>(h, trans, lengths, out, B, T);
}

// round 8
// speedup vs baseline: 1.0597x; 1.0597x over previous
#include <cuda_runtime.h>
#include <cuda_bf16.h>

#define NTAGS 64
#define LOG2E 1.4426950408889634f
#define LN2   0.69314718055994531f

__device__ __forceinline__ float fast_ex2(float x) {
    float r; asm("ex2.approx.ftz.f32 %0, %1;" : "=f"(r) : "f"(x)); return r;
}
__device__ __forceinline__ float fast_lg2(float x) {
    float r; asm("lg2.approx.ftz.f32 %0, %1;" : "=f"(r) : "f"(x)); return r;
}
__device__ __forceinline__ void fma2(unsigned long long& d, unsigned long long a, unsigned long long b) {
    asm("fma.rn.f32x2 %0, %1, %2, %0;" : "+l"(d) : "l"(a), "l"(b));
}
__device__ __forceinline__ unsigned long long add2(unsigned long long a, unsigned long long b) {
    unsigned long long r; asm("add.rn.f32x2 %0, %1, %2;" : "=l"(r) : "l"(a), "l"(b)); return r;
}
__device__ __forceinline__ unsigned long long pack2(float x, float y) {
    unsigned long long r; asm("mov.b64 %0, {%1, %2};" : "=l"(r) : "f"(x), "f"(y)); return r;
}
__device__ __forceinline__ float2 unpack2(unsigned long long v) {
    float2 f; asm("mov.b64 {%0, %1}, %2;" : "=f"(f.x), "=f"(f.y) : "l"(v)); return f;
}

// Named barrier over 64 threads (one group = 2 warps).
#define GROUP_BAR(id) asm volatile("bar.sync %0, 64;" :: "r"(id) : "memory")

// Permutation of batch indices, sorted by length DESCENDING. Sorted pairing
// makes pair rounds ~ len/2 instead of max(len_a,len_b)/2 (-25% aggregate),
// and descending order puts the longest pairs one-per-SM in wave 1 with only
// the SHORTEST pairs co-resident (they drain fast, leaving the critical chain
// to run solo).
__device__ int g_perm[8192];

__global__ void sort_len_kernel(const int* __restrict__ lengths, int B) {
    const int K = 1024;
    __shared__ unsigned long long key[K];
    const int tid = threadIdx.x;
    if (B > K) {                       // fallback: identity (still correct)
        for (int i = tid; i < B && i < 8192; i += blockDim.x) g_perm[i] = i;
        return;
    }
    unsigned long long v = (tid < B)
        ? (((unsigned long long)(unsigned)lengths[tid] << 13) | (unsigned)tid)
        : 0ull;                        // pad sinks to the end (real len >= 1)
    key[tid] = v;
    __syncthreads();
    for (int k = 2; k <= K; k <<= 1) {
        for (int j = k >> 1; j > 0; j >>= 1) {
            int l = tid ^ j;
            if (l > tid) {
                unsigned long long a = key[tid], b = key[l];
                bool up = ((tid & k) == 0);          // descending subsequence
                if (up ? (a < b) : (a > b)) { key[tid] = b; key[l] = a; }
            }
            __syncthreads();
        }
    }
    unsigned long long v2 = key[tid];
    g_perm[tid] = (v2 >> 13) ? (int)(v2 & 0x1FFF) : -1;
}

// One CTA (128 threads) = ONE batch pair (similar lengths via g_perm), TIME-SPLIT:
//   group 0 (warps 0,1 / SMSP 0,1): FORWARD   P <- diag(f_t) E P, t ascending
//   group 1 (warps 2,3 / SMSP 2,3): BACKWARD  A <- E^T (f_t (*) A), t descending
// Groups sync only with themselves (named barriers) and run only their own
// round count (fwd: ceil(len/2), bwd: floor(len/2)).
//
// Linear-domain normalization per round: divide stored vector by its element 0
// (q), accumulate lg2(q); emission factor folded via ex2(emit*log2e - lg2 q) on
// MUFU, overlapped with the 64-term f32x2 dot. Backward state carries one extra
// folded emission, divided out in the epilogue.
// answer = LN2 * (m2F + m2B + lg2(dot(P, A))).
__global__ __launch_bounds__(128, 2)
void crf_fwd_kernel(const float* __restrict__ h, const float* __restrict__ trans,
                    const int* __restrict__ lengths, float* __restrict__ out,
                    int B, int T)
{
    const int tid   = threadIdx.x;
    const int g     = tid >> 6;            // 0 = forward, 1 = backward
    const int tag   = tid & 63;
    const int dir   = g;
    const int barid = g + 1;

    const int b0v = g_perm[2 * blockIdx.x];
    const int b1v = g_perm[2 * blockIdx.x + 1];
    const bool valid0 = (b0v >= 0);
    const bool valid1 = (b1v >= 0);
    const int b0 = valid0 ? b0v : 0;
    const int b1 = valid1 ? b1v : 0;

    __shared__ __align__(16) unsigned long long pbuf[2][2][NTAGS]; // [group][buf][tag]
    __shared__ __align__(16) unsigned long long fin[2][NTAGS];     // final vectors
    __shared__ float2 fm2[2];                                      // log2 normalizer sums

    const int len0 = valid0 ? lengths[b0] : 0;
    const int len1 = valid1 ? lengths[b1] : 0;
    const int mid0 = (len0 + 1) >> 1;
    const int mid1 = (len1 + 1) >> 1;
    const int act0 = dir ? (len0 - mid0) : mid0;  // active rounds per component
    const int act1 = dir ? (len1 - mid1) : mid1;
    const int rounds = max(act0, act1);           // group-local bound

    // cache exp(trans): fwd lanes cache row `tag`, bwd lanes cache column `tag`
    unsigned long long rowp[NTAGS];
    {
        const int base   = dir ? tag : tag * NTAGS;
        const int stride = dir ? NTAGS : 1;
        #pragma unroll
        for (int j = 0; j < NTAGS; j++) {
            float e = fast_ex2(trans[base + j * stride] * LOG2E);
            rowp[j] = pack2(e, e);
        }
    }

    const float* __restrict__ hb0 = h + (size_t)b0 * T * NTAGS + tag;
    const float* __restrict__ hb1 = h + (size_t)b1 * T * NTAGS + tag;

    // initial state
    float px, py, el0 = 0.0f, el1 = 0.0f;  // el* = most recent folded emission (bwd)
    if (dir == 0) {
        px = (tag == NTAGS - 2) ? 1.0f : 0.0f;   // START_TAG = N-2
        py = px;
    } else {
        float uval = fast_ex2(trans[(NTAGS - 1) * NTAGS + tag] * LOG2E); // END row
        el0 = hb0[(size_t)max(len0 - 1, 0) * NTAGS];
        el1 = hb1[(size_t)max(len1 - 1, 0) * NTAGS];
        px = uval * fast_ex2(el0 * LOG2E);
        py = uval * fast_ex2(el1 * LOG2E);
    }
    float m20 = 0.0f, m21 = 0.0f;

    pbuf[g][0][tag] = pack2(px, py);
    GROUP_BAR(barid);

    // emission pipeline, 2 deep. index at round r: fwd r ; bwd max(len-2-r, 0)
    const int Tm1 = T - 1;
    int i0a = dir ? max(len0 - 2, 0) : 0;
    int i1a = dir ? max(len1 - 2, 0) : 0;
    int i0b = dir ? max(len0 - 3, 0) : min(1, Tm1);
    int i1b = dir ? max(len1 - 3, 0) : min(1, Tm1);
    float ea0 = hb0[(size_t)i0a * NTAGS];
    float ea1 = hb1[(size_t)i1a * NTAGS];
    float eb0 = hb0[(size_t)i0b * NTAGS];
    float eb1 = hb1[(size_t)i1b * NTAGS];

    int buf = 0;
    for (int r = 0; r < rounds; r++) {
        const ulonglong2* Pv = reinterpret_cast<const ulonglong2*>(pbuf[g][buf]);

        ulonglong2 u0 = Pv[0], u1 = Pv[1], u2 = Pv[2], u3 = Pv[3];
        float2 qq = unpack2(u0.x);                 // normalizer q = vec[0]
        const bool q1sel = (dir == 0) & (r == 0);  // fwd round 0: vec[0] == 0
        float qx = q1sel ? 1.0f : qq.x;
        float qy = q1sel ? 1.0f : qq.y;

        unsigned long long a0 = 0, a1 = 0, a2 = 0, a3 = 0;
        unsigned long long a4 = 0, a5 = 0, a6 = 0, a7 = 0;
        fma2(a0, rowp[0], u0.x); fma2(a1, rowp[1], u0.y);
        fma2(a2, rowp[2], u1.x); fma2(a3, rowp[3], u1.y);
        fma2(a4, rowp[4], u2.x); fma2(a5, rowp[5], u2.y);
        fma2(a6, rowp[6], u3.x); fma2(a7, rowp[7], u3.y);

        // normalizer + emission factor on MUFU, overlapped with the dot
        float l2x = fast_lg2(qx);
        float l2y = fast_lg2(qy);
        float rx  = fast_ex2(fmaf(ea0, LOG2E, -l2x));
        float ry  = fast_ex2(fmaf(ea1, LOG2E, -l2y));

        #pragma unroll
        for (int k = 4; k < 32; k += 4) {
            ulonglong2 v0 = Pv[k],     v1 = Pv[k + 1];
            ulonglong2 v2 = Pv[k + 2], v3 = Pv[k + 3];
            fma2(a0, rowp[2 * k + 0], v0.x); fma2(a1, rowp[2 * k + 1], v0.y);
            fma2(a2, rowp[2 * k + 2], v1.x); fma2(a3, rowp[2 * k + 3], v1.y);
            fma2(a4, rowp[2 * k + 4], v2.x); fma2(a5, rowp[2 * k + 5], v2.y);
            fma2(a6, rowp[2 * k + 6], v3.x); fma2(a7, rowp[2 * k + 7], v3.y);
        }

        // prefetch emissions for round r+2 (clamped, memory-safe)
        int n0 = dir ? max(len0 - 4 - r, 0) : min(r + 2, Tm1);
        int n1 = dir ? max(len1 - 4 - r, 0) : min(r + 2, Tm1);
        float ec0 = hb0[(size_t)n0 * NTAGS];
        float ec1 = hb1[(size_t)n1 * NTAGS];

        float2 S = unpack2(add2(add2(add2(a0, a1), add2(a2, a3)),
                                add2(add2(a4, a5), add2(a6, a7))));

        // masked update (freeze past this component's active rounds)
        const bool k0 = r < act0;
        const bool k1 = r < act1;
        px   = k0 ? S.x * rx : px;   m20 += k0 ? l2x : 0.0f;
        py   = k1 ? S.y * ry : py;   m21 += k1 ? l2y : 0.0f;
        el0  = k0 ? ea0 : el0;       // emission currently folded (bwd bookkeeping)
        el1  = k1 ? ea1 : el1;

        pbuf[g][buf ^ 1][tag] = pack2(px, py);
        GROUP_BAR(barid);

        ea0 = eb0; ea1 = eb1;
        eb0 = ec0; eb1 = ec1;
        buf ^= 1;
    }

    // Backward state carries one extra folded emission: divide it out.
    float c0 = dir ? fast_ex2(-el0 * LOG2E) : 1.0f;
    float c1 = dir ? fast_ex2(-el1 * LOG2E) : 1.0f;
    fin[g][tag] = pack2(px * c0, py * c1);
    if (tag == 0) fm2[g] = make_float2(m20, m21);
    __syncthreads();

    // Epilogue: warp 0 reduces. answer = LN2*(m2F + m2B + lg2(F . A)).
    if (tid < 32) {
        float2 Fa = unpack2(fin[0][tid]);
        float2 Fb = unpack2(fin[0][tid + 32]);
        float2 Aa = unpack2(fin[1][tid]);
        float2 Ab = unpack2(fin[1][tid + 32]);
        float sx = Fa.x * Aa.x + Fb.x * Ab.x;
        float sy = Fa.y * Aa.y + Fb.y * Ab.y;
        #pragma unroll
        for (int o = 16; o > 0; o >>= 1) {
            sx += __shfl_xor_sync(0xffffffffu, sx, o);
            sy += __shfl_xor_sync(0xffffffffu, sy, o);
        }
        if (tid == 0) {
            float2 mF = fm2[0];
            float2 mB = fm2[1];
            if (valid0) out[b0v] = LN2 * (mF.x + mB.x + fast_lg2(sx));
            if (valid1) out[b1v] = LN2 * (mF.y + mB.y + fast_lg2(sy));
        }
    }
}

extern "C" void kernel_launch(void* const* d_in, const int* in_sizes, int n_in,
                              void* d_out, int out_size)
{
    const float* h       = (const float*)d_in[0];   // [B, T, N] f32
    const float* trans   = (const float*)d_in[1];   // [N, N]    f32
    const int*   lengths = (const int*)d_in[2];     // [B]       i32
    float*       out     = (float*)d_out;           // [B]       f32

    const int B = in_sizes[2];
    const int T = in_sizes[0] / (B * NTAGS);

    sort_len_kernel<<<1, 1024>>>(lengths, B);

    const int nblk = (B + 1) / 2;
    crf_fwd_kernel<<<nblk, 128>>>(h, trans, lengths, out, B, T);
}

// round 9
// speedup vs baseline: 1.4880x; 1.4041x over previous
#include <cuda_runtime.h>
#include <cuda_bf16.h>

#define NTAGS 64
#define LOG2E 1.4426950408889634f
#define LN2   0.69314718055994531f

__device__ __forceinline__ float fast_ex2(float x) {
    float r; asm("ex2.approx.ftz.f32 %0, %1;" : "=f"(r) : "f"(x)); return r;
}
__device__ __forceinline__ float fast_lg2(float x) {
    float r; asm("lg2.approx.ftz.f32 %0, %1;" : "=f"(r) : "f"(x)); return r;
}
__device__ __forceinline__ void fma2(unsigned long long& d, unsigned long long a, unsigned long long b) {
    asm("fma.rn.f32x2 %0, %1, %2, %0;" : "+l"(d) : "l"(a), "l"(b));
}
__device__ __forceinline__ unsigned long long add2(unsigned long long a, unsigned long long b) {
    unsigned long long r; asm("add.rn.f32x2 %0, %1, %2;" : "=l"(r) : "l"(a), "l"(b)); return r;
}
__device__ __forceinline__ unsigned long long pack2(float x, float y) {
    unsigned long long r; asm("mov.b64 %0, {%1, %2};" : "=l"(r) : "f"(x), "f"(y)); return r;
}
__device__ __forceinline__ float2 unpack2(unsigned long long v) {
    float2 f; asm("mov.b64 {%0, %1}, %2;" : "=f"(f.x), "=f"(f.y) : "l"(v)); return f;
}

// Batch indices sorted by length DESCENDING (wave packing + equal-length pairing).
__device__ int g_perm[8192];

__global__ void sort_len_kernel(const int* __restrict__ lengths, int B) {
    const int K = 1024;
    __shared__ unsigned long long key[K];
    const int tid = threadIdx.x;
    if (B > K) {                       // fallback: identity (still correct)
        for (int i = tid; i < B && i < 8192; i += blockDim.x) g_perm[i] = i;
        return;
    }
    unsigned long long v = (tid < B)
        ? (((unsigned long long)(unsigned)lengths[tid] << 13) | (unsigned)tid)
        : 0ull;                        // pad sinks to the end (real len >= 1)
    key[tid] = v;
    __syncthreads();
    for (int k = 2; k <= K; k <<= 1) {
        for (int j = k >> 1; j > 0; j >>= 1) {
            int l = tid ^ j;
            if (l > tid) {
                unsigned long long a = key[tid], b = key[l];
                bool up = ((tid & k) == 0);          // descending subsequence
                if (up ? (a < b) : (a > b)) { key[tid] = b; key[l] = a; }
            }
            __syncthreads();
        }
    }
    unsigned long long v2 = key[tid];
    g_perm[tid] = (v2 >> 13) ? (int)(v2 & 0x1FFF) : -1;
}

// One CTA (128 threads) = 2 batches x {forward, backward} = 4 SELF-CONTAINED warps.
//   warp 0: batch0 fwd (SMSP0)   warp 1: batch0 bwd (SMSP1)
//   warp 2: batch1 fwd (SMSP2)   warp 3: batch1 bwd (SMSP3)
// No cross-warp sync in the mainloop: each warp exchanges its 64-float state
// through its OWN smem buffer with one __syncwarp per round. Every round is
// active (per-warp exact trip count), no masking, no barrier skew.
//
// Lane l owns tags t0=2l, t1=2l+1. f32x2 packs ADJACENT j-columns:
//   acc_t += (E[t][2j],E[t][2j+1]) * (p_{2j},p_{2j+1});  S_t = acc.x+acc.y
// fwd:  P <- diag(f_r) E P            (emission index r, ascending)
// bwd:  A <- f (*) E^T A              (emission index len-2-r, descending;
//        init folds END row * e_{len-1}; last folded emission divided out)
// Normalization per round: q = P[0]; p /= q in linear domain via
// ex2(emit*log2e - lg2 q); m2 += lg2 q.  answer = LN2*(m2F+m2B+lg2(F.A)).
__global__ __launch_bounds__(128, 2)
void crf_fwd_kernel(const float* __restrict__ h, const float* __restrict__ trans,
                    const int* __restrict__ lengths, float* __restrict__ out,
                    int B, int T)
{
    const int tid = threadIdx.x;
    const int w   = tid >> 5;
    const int l   = tid & 31;
    const int dir = w & 1;                  // 0 = forward, 1 = backward
    const int slot = w >> 1;                // which batch of the pair
    const int t0 = 2 * l;
    const int t1 = 2 * l + 1;

    const int bv = g_perm[2 * blockIdx.x + slot];
    const bool valid = (bv >= 0);
    const int b   = valid ? bv : 0;
    const int len = valid ? lengths[b] : 1;
    const int mid = (len + 1) >> 1;
    const int rounds = dir ? (len - mid) : mid;   // exact per-warp trip count

    __shared__ __align__(16) float pbuf[4][2][NTAGS]; // per-warp double buffer
    __shared__ __align__(16) float fin[4][NTAGS];
    __shared__ float fm2[4];

    // E cache: 64 u64 regs, (two adjacent j-values) per register, rows t0/t1
    // for fwd, columns t0/t1 for bwd.
    unsigned long long E0[32], E1[32];
    if (dir == 0) {
        const float4* r0p = reinterpret_cast<const float4*>(trans + t0 * NTAGS);
        const float4* r1p = reinterpret_cast<const float4*>(trans + t1 * NTAGS);
        #pragma unroll
        for (int k = 0; k < 16; k++) {
            float4 a = r0p[k], c = r1p[k];
            E0[2 * k]     = pack2(fast_ex2(a.x * LOG2E), fast_ex2(a.y * LOG2E));
            E0[2 * k + 1] = pack2(fast_ex2(a.z * LOG2E), fast_ex2(a.w * LOG2E));
            E1[2 * k]     = pack2(fast_ex2(c.x * LOG2E), fast_ex2(c.y * LOG2E));
            E1[2 * k + 1] = pack2(fast_ex2(c.z * LOG2E), fast_ex2(c.w * LOG2E));
        }
    } else {
        #pragma unroll
        for (int j2 = 0; j2 < 32; j2++) {
            E0[j2] = pack2(fast_ex2(trans[(2 * j2) * NTAGS + t0] * LOG2E),
                           fast_ex2(trans[(2 * j2 + 1) * NTAGS + t0] * LOG2E));
            E1[j2] = pack2(fast_ex2(trans[(2 * j2) * NTAGS + t1] * LOG2E),
                           fast_ex2(trans[(2 * j2 + 1) * NTAGS + t1] * LOG2E));
        }
    }

    const float* __restrict__ hb = h + (size_t)b * T * NTAGS;

    // initial state
    float px0, px1, m2 = 0.0f, el0 = 0.0f, el1 = 0.0f;
    if (dir == 0) {
        px0 = (t0 == NTAGS - 2) ? 1.0f : 0.0f;   // START_TAG = 62 (even)
        px1 = 0.0f;
    } else {
        float u0 = fast_ex2(trans[(NTAGS - 1) * NTAGS + t0] * LOG2E);
        float u1 = fast_ex2(trans[(NTAGS - 1) * NTAGS + t1] * LOG2E);
        float2 ei = *reinterpret_cast<const float2*>(hb + (size_t)(len - 1) * NTAGS + t0);
        el0 = ei.x; el1 = ei.y;
        px0 = u0 * fast_ex2(el0 * LOG2E);
        px1 = u1 * fast_ex2(el1 * LOG2E);
    }
    *reinterpret_cast<float2*>(&pbuf[w][0][t0]) = make_float2(px0, px1);
    __syncwarp();

    // emission pipeline (2 deep): index at round r = fwd: r ; bwd: max(len-2-r,0)
    const int Tm1 = T - 1;
    const int ia = dir ? max(len - 2, 0) : 0;
    const int ib = dir ? max(len - 3, 0) : min(1, Tm1);
    float2 ea = *reinterpret_cast<const float2*>(hb + (size_t)ia * NTAGS + t0);
    float2 eb = *reinterpret_cast<const float2*>(hb + (size_t)ib * NTAGS + t0);

    int buf = 0;
    for (int r = 0; r < rounds; r++) {
        const ulonglong2* Pv = reinterpret_cast<const ulonglong2*>(&pbuf[w][buf][0]);

        ulonglong2 v0 = Pv[0];
        float2 qq = unpack2(v0.x);
        float q = ((dir == 0) & (r == 0)) ? 1.0f : qq.x;   // fwd round 0: P[0]==0

        unsigned long long a00 = 0, a01 = 0, a10 = 0, a11 = 0;
        fma2(a00, E0[0], v0.x); fma2(a10, E1[0], v0.x);
        fma2(a01, E0[1], v0.y); fma2(a11, E1[1], v0.y);

        // normalizer + emission factors on MUFU, overlapped with the dot
        float l2q = fast_lg2(q);
        float r0f = fast_ex2(fmaf(ea.x, LOG2E, -l2q));
        float r1f = fast_ex2(fmaf(ea.y, LOG2E, -l2q));

        #pragma unroll
        for (int k = 1; k < 16; k++) {
            ulonglong2 v = Pv[k];
            fma2(a00, E0[2 * k],     v.x); fma2(a10, E1[2 * k],     v.x);
            fma2(a01, E0[2 * k + 1], v.y); fma2(a11, E1[2 * k + 1], v.y);
        }

        // prefetch emissions for round r+2 (clamped, memory-safe)
        const int ni = dir ? max(len - 4 - r, 0) : min(r + 2, Tm1);
        float2 ec = *reinterpret_cast<const float2*>(hb + (size_t)ni * NTAGS + t0);

        float2 s0 = unpack2(add2(a00, a01));
        float2 s1 = unpack2(add2(a10, a11));
        float S0 = s0.x + s0.y;
        float S1 = s1.x + s1.y;

        px0 = S0 * r0f;
        px1 = S1 * r1f;
        m2 += l2q;
        el0 = ea.x; el1 = ea.y;        // most recent folded emission (bwd use)

        *reinterpret_cast<float2*>(&pbuf[w][buf ^ 1][t0]) = make_float2(px0, px1);
        __syncwarp();

        ea = eb; eb = ec;
        buf ^= 1;
    }

    // backward state carries one extra folded emission: divide it out
    float c0 = dir ? fast_ex2(-el0 * LOG2E) : 1.0f;
    float c1 = dir ? fast_ex2(-el1 * LOG2E) : 1.0f;
    *reinterpret_cast<float2*>(&fin[w][t0]) = make_float2(px0 * c0, px1 * c1);
    if (l == 0) fm2[w] = m2;
    __syncthreads();

    // Epilogue: warp p reduces batch p. answer = LN2*(m2F + m2B + lg2(F . A)).
    if (tid < 64) {
        const int p    = tid >> 5;
        const int lane = tid & 31;
        float sx = fin[2 * p][lane]      * fin[2 * p + 1][lane]
                 + fin[2 * p][lane + 32] * fin[2 * p + 1][lane + 32];
        #pragma unroll
        for (int o = 16; o > 0; o >>= 1)
            sx += __shfl_xor_sync(0xffffffffu, sx, o);
        if (lane == 0) {
            const int obv = g_perm[2 * blockIdx.x + p];
            if (obv >= 0)
                out[obv] = LN2 * (fm2[2 * p] + fm2[2 * p + 1] + fast_lg2(sx));
        }
    }
}

extern "C" void kernel_launch(void* const* d_in, const int* in_sizes, int n_in,
                              void* d_out, int out_size)
{
    const float* h       = (const float*)d_in[0];   // [B, T, N] f32
    const float* trans   = (const float*)d_in[1];   // [N, N]    f32
    const int*   lengths = (const int*)d_in[2];     // [B]       i32
    float*       out     = (float*)d_out;           // [B]       f32

    const int B = in_sizes[2];
    const int T = in_sizes[0] / (B * NTAGS);

    sort_len_kernel<<<1, 1024>>>(lengths, B);

    const int nblk = (B + 1) / 2;
    crf_fwd_kernel<<<nblk, 128>>>(h, trans, lengths, out, B, T);
}